// round 4
// baseline (speedup 1.0000x reference)
#include <cuda_runtime.h>
#include <cuda_bf16.h>

// Chebyshev (L-inf) pairwise distance: out[i,j] = max_d |A[i,d] - B[j,d]|
// A: [4096, 32] fp32, B: [4096, 32] fp32, out: [4096, 4096] fp32.
//
// R4: packed fp32x2 over the *i* axis. (a_i, a_{i+1}) pairs are naturally
// register-adjacent from LDS.128 of consecutive A rows; -B is stored
// DUPLICATED in smem so (nb_j, nb_j) pairs also come straight from LDS.128.
// One add.rn.f32x2 -> two diffs with zero operand-shuffle MOVs; scalar FMNMX
// with |src| modifier consumes the pair halves directly.

constexpr int D  = 32;
constexpr int TI = 128;   // rows per CTA tile
constexpr int TJ = 64;    // cols per CTA tile

__global__ __launch_bounds__(256, 2)
void cheby_kernel(const float* __restrict__ A, const float* __restrict__ B,
                  float* __restrict__ out, int M) {
    __shared__ float As[D][TI];        // As[d][r]        =  A[bi+r][d]
    __shared__ float Bsd[D][2 * TJ];   // Bsd[d][2c+{0,1}] = -B[bj+c][d]

    const int tid = threadIdx.x;
    const int bi  = blockIdx.y * TI;
    const int bj  = blockIdx.x * TJ;

    // A tile: 128 rows x 32 d = 1024 float4; 256 threads x 4.
    #pragma unroll
    for (int k = 0; k < 4; k++) {
        int idx = tid + k * 256;
        int row = idx >> 3;             // 8 float4 per 32-wide row
        int dg  = (idx & 7) << 2;
        float4 v = *reinterpret_cast<const float4*>(A + (size_t)(bi + row) * D + dg);
        As[dg + 0][row] = v.x; As[dg + 1][row] = v.y;
        As[dg + 2][row] = v.z; As[dg + 3][row] = v.w;
    }
    // B tile: 64 rows x 32 d = 512 float4; 256 threads x 2; negate + duplicate.
    #pragma unroll
    for (int k = 0; k < 2; k++) {
        int idx = tid + k * 256;
        int row = idx >> 3;
        int dg  = (idx & 7) << 2;
        float4 v = *reinterpret_cast<const float4*>(B + (size_t)(bj + row) * D + dg);
        Bsd[dg + 0][2*row] = -v.x; Bsd[dg + 0][2*row + 1] = -v.x;
        Bsd[dg + 1][2*row] = -v.y; Bsd[dg + 1][2*row + 1] = -v.y;
        Bsd[dg + 2][2*row] = -v.z; Bsd[dg + 2][2*row + 1] = -v.z;
        Bsd[dg + 3][2*row] = -v.w; Bsd[dg + 3][2*row + 1] = -v.w;
    }
    __syncthreads();

    const int tx = tid & 15;            // 16 x 4 cols = 64
    const int ty = tid >> 4;            // 16 x 8 rows = 128
    const int ri = ty * 8;
    const int rj = tx * 4;

    float acc[8][4];
    #pragma unroll
    for (int i = 0; i < 8; i++)
        #pragma unroll
        for (int j = 0; j < 4; j++)
            acc[i][j] = 0.0f;           // |diff| >= 0, so 0 is a safe identity

    #pragma unroll 8
    for (int d = 0; d < D; d++) {
        // 8 a-values as 4 natural pairs: (a0,a1)(a2,a3) | (a4,a5)(a6,a7)
        ulonglong2 ap0 = *reinterpret_cast<const ulonglong2*>(&As[d][ri]);
        ulonglong2 ap1 = *reinterpret_cast<const ulonglong2*>(&As[d][ri + 4]);
        // 4 negated-b values as duplicated pairs: (nb0,nb0)(nb1,nb1) | (nb2,nb2)(nb3,nb3)
        ulonglong2 bp0 = *reinterpret_cast<const ulonglong2*>(&Bsd[d][2 * rj]);
        ulonglong2 bp1 = *reinterpret_cast<const ulonglong2*>(&Bsd[d][2 * rj + 4]);

        unsigned long long ap[4] = {ap0.x, ap0.y, ap1.x, ap1.y};
        #pragma unroll
        for (int p = 0; p < 4; p++) {   // pair p covers rows 2p, 2p+1
            unsigned long long s0, s1, s2, s3;
            asm("add.rn.f32x2 %0, %1, %2;" : "=l"(s0) : "l"(ap[p]), "l"(bp0.x));
            asm("add.rn.f32x2 %0, %1, %2;" : "=l"(s1) : "l"(ap[p]), "l"(bp0.y));
            asm("add.rn.f32x2 %0, %1, %2;" : "=l"(s2) : "l"(ap[p]), "l"(bp1.x));
            asm("add.rn.f32x2 %0, %1, %2;" : "=l"(s3) : "l"(ap[p]), "l"(bp1.y));
            float l0, h0, l1, h1, l2, h2, l3, h3;
            asm("mov.b64 {%0, %1}, %2;" : "=f"(l0), "=f"(h0) : "l"(s0));
            asm("mov.b64 {%0, %1}, %2;" : "=f"(l1), "=f"(h1) : "l"(s1));
            asm("mov.b64 {%0, %1}, %2;" : "=f"(l2), "=f"(h2) : "l"(s2));
            asm("mov.b64 {%0, %1}, %2;" : "=f"(l3), "=f"(h3) : "l"(s3));
            acc[2*p + 0][0] = fmaxf(acc[2*p + 0][0], fabsf(l0));
            acc[2*p + 1][0] = fmaxf(acc[2*p + 1][0], fabsf(h0));
            acc[2*p + 0][1] = fmaxf(acc[2*p + 0][1], fabsf(l1));
            acc[2*p + 1][1] = fmaxf(acc[2*p + 1][1], fabsf(h1));
            acc[2*p + 0][2] = fmaxf(acc[2*p + 0][2], fabsf(l2));
            acc[2*p + 1][2] = fmaxf(acc[2*p + 1][2], fabsf(h2));
            acc[2*p + 0][3] = fmaxf(acc[2*p + 0][3], fabsf(l3));
            acc[2*p + 1][3] = fmaxf(acc[2*p + 1][3], fabsf(h3));
        }
    }

    #pragma unroll
    for (int i = 0; i < 8; i++) {
        float* p = out + (size_t)(bi + ri + i) * M + (bj + rj);
        *reinterpret_cast<float4*>(p) =
            make_float4(acc[i][0], acc[i][1], acc[i][2], acc[i][3]);
    }
}

extern "C" void kernel_launch(void* const* d_in, const int* in_sizes, int n_in,
                              void* d_out, int out_size) {
    const float* A = (const float*)d_in[0];
    const float* B = (const float*)d_in[1];
    float* out = (float*)d_out;
    int N = in_sizes[0] / D;   // 4096
    int M = in_sizes[1] / D;   // 4096
    dim3 grid(M / TJ, N / TI); // 64 x 32 = 2048 CTAs -> ~6.9 waves
    cheby_kernel<<<grid, 256>>>(A, B, out, M);
}

// round 6
// speedup vs baseline: 1.0446x; 1.0446x over previous
#include <cuda_runtime.h>
#include <cuda_bf16.h>

// Chebyshev (L-inf) pairwise distance: out[i,j] = max_d |A[i,d] - B[j,d]|
// A: [4096, 32] fp32, B: [4096, 32] fp32, out: [4096, 4096] fp32.
//
// R6 = R5 resubmitted (R5 bench was an infra failure, theory untested):
//  - (a_i, a_{i+1}) pairs come register-adjacent from LDS.128 of As[d][ri..].
//  - -B is stored duplicated in a PLANAR layout Bdup[d][p][t][4] so thread tx
//    reads each plane at byte offset 16*tx -> contiguous 256B per quarter-warp,
//    zero bank conflicts (R4 read at 32B stride -> 4-way conflicts, L1=91%).
//  - 8x8 per-thread block: 102 instr / 64 outputs*d = 1.59 instr/output*d
//    vs the 2.55 effective measured in R1.

constexpr int D    = 32;
constexpr int TILE = 128;

__global__ __launch_bounds__(256, 2)
void cheby_kernel(const float* __restrict__ A, const float* __restrict__ B,
                  float* __restrict__ out, int M) {
    __shared__ float As[D][TILE];          // As[d][r] = A[bi+r][d]
    // Bdup[d][p][t][0..3] = (-b[8t+2p], -b[8t+2p], -b[8t+2p+1], -b[8t+2p+1])
    // where b[c] = B[bj+c][d]. Thread tx reads plane p at [d][p][tx] (16B).
    __shared__ float Bdup[D][4][16][4];

    const int tid = threadIdx.x;
    const int bi  = blockIdx.y * TILE;
    const int bj  = blockIdx.x * TILE;

    // A tile: 1024 float4, 256 threads x 4; transpose to d-major.
    #pragma unroll
    for (int k = 0; k < 4; k++) {
        int idx = tid + k * 256;
        int row = idx >> 3;                 // 8 float4 per 32-wide row
        int dg  = (idx & 7) << 2;
        float4 v = *reinterpret_cast<const float4*>(A + (size_t)(bi + row) * D + dg);
        As[dg + 0][row] = v.x; As[dg + 1][row] = v.y;
        As[dg + 2][row] = v.z; As[dg + 3][row] = v.w;
    }
    // B tile: 1024 float4, 256 threads x 4; negate + duplicate into planes.
    #pragma unroll
    for (int k = 0; k < 4; k++) {
        int idx = tid + k * 256;
        int c   = idx >> 3;                 // B row within tile (0..127)
        int dg  = (idx & 7) << 2;
        int t   = c >> 3;                   // plane column
        int p   = (c >> 1) & 3;             // plane index
        int e   = (c & 1) << 1;             // 0 or 2: position inside 16B block
        float4 v = *reinterpret_cast<const float4*>(B + (size_t)(bj + c) * D + dg);
        Bdup[dg + 0][p][t][e] = -v.x; Bdup[dg + 0][p][t][e + 1] = -v.x;
        Bdup[dg + 1][p][t][e] = -v.y; Bdup[dg + 1][p][t][e + 1] = -v.y;
        Bdup[dg + 2][p][t][e] = -v.z; Bdup[dg + 2][p][t][e + 1] = -v.z;
        Bdup[dg + 3][p][t][e] = -v.w; Bdup[dg + 3][p][t][e + 1] = -v.w;
    }
    __syncthreads();

    const int tx = tid & 15;                // 16 x 8 cols = 128
    const int ty = tid >> 4;                // 16 x 8 rows = 128
    const int ri = ty * 8;
    const int rj = tx * 8;                  // j block = 8*tx .. 8*tx+7

    float acc[8][8];
    #pragma unroll
    for (int i = 0; i < 8; i++)
        #pragma unroll
        for (int j = 0; j < 8; j++)
            acc[i][j] = 0.0f;               // |diff| >= 0: safe identity

    #pragma unroll 4
    for (int d = 0; d < D; d++) {
        // 8 a-values = 4 natural pairs (broadcast LDS, conflict-free).
        ulonglong2 aq0 = *reinterpret_cast<const ulonglong2*>(&As[d][ri]);
        ulonglong2 aq1 = *reinterpret_cast<const ulonglong2*>(&As[d][ri + 4]);
        // 8 duplicated -b pairs from 4 planes (contiguous 16B*tx, conflict-free).
        ulonglong2 bq0 = *reinterpret_cast<const ulonglong2*>(&Bdup[d][0][tx][0]);
        ulonglong2 bq1 = *reinterpret_cast<const ulonglong2*>(&Bdup[d][1][tx][0]);
        ulonglong2 bq2 = *reinterpret_cast<const ulonglong2*>(&Bdup[d][2][tx][0]);
        ulonglong2 bq3 = *reinterpret_cast<const ulonglong2*>(&Bdup[d][3][tx][0]);

        unsigned long long ap[4] = {aq0.x, aq0.y, aq1.x, aq1.y};
        // bp[q] duplicates -b_{rj+q}:  plane p=q>>1, element e=q&1.
        unsigned long long bp[8] = {bq0.x, bq0.y, bq1.x, bq1.y,
                                    bq2.x, bq2.y, bq3.x, bq3.y};

        #pragma unroll
        for (int p = 0; p < 4; p++) {       // row pair (2p, 2p+1)
            #pragma unroll
            for (int q = 0; q < 8; q++) {   // column rj+q
                unsigned long long s;
                asm("add.rn.f32x2 %0, %1, %2;" : "=l"(s) : "l"(ap[p]), "l"(bp[q]));
                float lo, hi;
                asm("mov.b64 {%0, %1}, %2;" : "=f"(lo), "=f"(hi) : "l"(s));
                acc[2*p + 0][q] = fmaxf(acc[2*p + 0][q], fabsf(lo));
                acc[2*p + 1][q] = fmaxf(acc[2*p + 1][q], fabsf(hi));
            }
        }
    }

    #pragma unroll
    for (int i = 0; i < 8; i++) {
        float* po = out + (size_t)(bi + ri + i) * M + (bj + rj);
        *reinterpret_cast<float4*>(po + 0) =
            make_float4(acc[i][0], acc[i][1], acc[i][2], acc[i][3]);
        *reinterpret_cast<float4*>(po + 4) =
            make_float4(acc[i][4], acc[i][5], acc[i][6], acc[i][7]);
    }
}

extern "C" void kernel_launch(void* const* d_in, const int* in_sizes, int n_in,
                              void* d_out, int out_size) {
    const float* A = (const float*)d_in[0];
    const float* B = (const float*)d_in[1];
    float* out = (float*)d_out;
    int N = in_sizes[0] / D;   // 4096
    int M = in_sizes[1] / D;   // 4096
    dim3 grid(M / TILE, N / TILE);  // 32 x 32 = 1024 CTAs
    cheby_kernel<<<grid, 256>>>(A, B, out, M);
}

// round 7
// speedup vs baseline: 1.0702x; 1.0245x over previous
#include <cuda_runtime.h>
#include <cuda_bf16.h>

// Chebyshev (L-inf) pairwise distance: out[i,j] = max_d |A[i,d] - B[j,d]|
// A: [4096, 32] fp32, B: [4096, 32] fp32, out: [4096, 4096] fp32.
//
// R7 = lean packed-f32x2 stream (R6) x high occupancy (R2):
//  - 8x4 per-thread block, 512 threads, 128x128 tile -> ~58 regs,
//    __launch_bounds__(512,2) -> 32 warps/SM (R6 died at 16 warps).
//  - (a_i, a_{i+1}) pairs register-adjacent from LDS.128 of As[d][ri..];
//    A reads are full-warp broadcast (all lanes share ty) -> ~free.
//  - -B duplicated in planar layout Bdup[d][p][t][4]; thread tx reads 16B at
//    offset 16*tx -> contiguous 512B per warp, zero bank conflicts.
//  - 52 instr / 32 outputs*d = 1.63 instr/output*d.

constexpr int D    = 32;
constexpr int TILE = 128;

__global__ __launch_bounds__(512, 2)
void cheby_kernel(const float* __restrict__ A, const float* __restrict__ B,
                  float* __restrict__ out, int M) {
    __shared__ float As[D][TILE];        // As[d][r] = A[bi+r][d]           (16 KB)
    // Bdup[d][p][t][0..3] = (-b[4t+2p], -b[4t+2p], -b[4t+2p+1], -b[4t+2p+1])
    // where b[c] = B[bj+c][d].  Thread tx reads [d][p][tx] (16B).     (32 KB)
    __shared__ float Bdup[D][2][32][4];

    const int tid = threadIdx.x;
    const int bi  = blockIdx.y * TILE;
    const int bj  = blockIdx.x * TILE;

    // A tile: 1024 float4, 512 threads x 2; transpose to d-major.
    #pragma unroll
    for (int k = 0; k < 2; k++) {
        int idx = tid + k * 512;
        int row = idx >> 3;                 // 8 float4 per 32-wide row
        int dg  = (idx & 7) << 2;
        float4 v = *reinterpret_cast<const float4*>(A + (size_t)(bi + row) * D + dg);
        As[dg + 0][row] = v.x; As[dg + 1][row] = v.y;
        As[dg + 2][row] = v.z; As[dg + 3][row] = v.w;
    }
    // B tile: 1024 float4, 512 threads x 2; negate + duplicate into planes.
    #pragma unroll
    for (int k = 0; k < 2; k++) {
        int idx = tid + k * 512;
        int c   = idx >> 3;                 // B row within tile (0..127)
        int dg  = (idx & 7) << 2;
        int t   = c >> 2;                   // slot (0..31)
        int p   = (c >> 1) & 1;             // plane (0..1)
        int e   = (c & 1) << 1;             // 0 or 2 inside the 16B block
        float4 v = *reinterpret_cast<const float4*>(B + (size_t)(bj + c) * D + dg);
        Bdup[dg + 0][p][t][e] = -v.x; Bdup[dg + 0][p][t][e + 1] = -v.x;
        Bdup[dg + 1][p][t][e] = -v.y; Bdup[dg + 1][p][t][e + 1] = -v.y;
        Bdup[dg + 2][p][t][e] = -v.z; Bdup[dg + 2][p][t][e + 1] = -v.z;
        Bdup[dg + 3][p][t][e] = -v.w; Bdup[dg + 3][p][t][e + 1] = -v.w;
    }
    __syncthreads();

    const int tx = tid & 31;                // 32 x 4 cols = 128
    const int ty = tid >> 5;                // 16 x 8 rows = 128
    const int ri = ty * 8;
    const int rj = tx * 4;

    float acc[8][4];
    #pragma unroll
    for (int i = 0; i < 8; i++)
        #pragma unroll
        for (int j = 0; j < 4; j++)
            acc[i][j] = 0.0f;               // |diff| >= 0: safe identity

    #pragma unroll 4
    for (int d = 0; d < D; d++) {
        // 8 a-values = 4 natural pairs; same address across the warp (broadcast).
        ulonglong2 aq0 = *reinterpret_cast<const ulonglong2*>(&As[d][ri]);
        ulonglong2 aq1 = *reinterpret_cast<const ulonglong2*>(&As[d][ri + 4]);
        // 4 duplicated -b pairs from 2 planes (16B * tx, conflict-free).
        ulonglong2 bq0 = *reinterpret_cast<const ulonglong2*>(&Bdup[d][0][tx][0]);
        ulonglong2 bq1 = *reinterpret_cast<const ulonglong2*>(&Bdup[d][1][tx][0]);

        unsigned long long ap[4] = {aq0.x, aq0.y, aq1.x, aq1.y};
        // bp[q] duplicates -b_{rj+q}.
        unsigned long long bp[4] = {bq0.x, bq0.y, bq1.x, bq1.y};

        #pragma unroll
        for (int p = 0; p < 4; p++) {       // row pair (2p, 2p+1)
            #pragma unroll
            for (int q = 0; q < 4; q++) {   // column rj+q
                unsigned long long s;
                asm("add.rn.f32x2 %0, %1, %2;" : "=l"(s) : "l"(ap[p]), "l"(bp[q]));
                float lo, hi;
                asm("mov.b64 {%0, %1}, %2;" : "=f"(lo), "=f"(hi) : "l"(s));
                acc[2*p + 0][q] = fmaxf(acc[2*p + 0][q], fabsf(lo));
                acc[2*p + 1][q] = fmaxf(acc[2*p + 1][q], fabsf(hi));
            }
        }
    }

    #pragma unroll
    for (int i = 0; i < 8; i++) {
        float* po = out + (size_t)(bi + ri + i) * M + (bj + rj);
        *reinterpret_cast<float4*>(po) =
            make_float4(acc[i][0], acc[i][1], acc[i][2], acc[i][3]);
    }
}

extern "C" void kernel_launch(void* const* d_in, const int* in_sizes, int n_in,
                              void* d_out, int out_size) {
    const float* A = (const float*)d_in[0];
    const float* B = (const float*)d_in[1];
    float* out = (float*)d_out;
    int N = in_sizes[0] / D;   // 4096
    int M = in_sizes[1] / D;   // 4096
    dim3 grid(M / TILE, N / TILE);  // 32 x 32 = 1024 CTAs
    cheby_kernel<<<grid, 512>>>(A, B, out, M);
}